// round 7
// baseline (speedup 1.0000x reference)
#include <cuda_runtime.h>
#include <cuda_fp16.h>
#include <math.h>
#include <stdint.h>

#define DM  256
#define SEQ 2304       // 48*48
#define NB  16

// Projected Q, K, V stored as fp16 (18 MB each)
__device__ __half g_Q[NB * SEQ * DM];
__device__ __half g_K[NB * SEQ * DM];
__device__ __half g_V[NB * SEQ * DM];

// ---------------------------------------------------------------------------
// helpers (sm_80-era PTX: legal on plain sm_103 target)
// ---------------------------------------------------------------------------
__device__ __forceinline__ uint32_t smem_u32(const void* p) {
    uint32_t a;
    asm("{ .reg .u64 t; cvta.to.shared.u64 t, %1; cvt.u32.u64 %0, t; }"
        : "=r"(a) : "l"(p));
    return a;
}
__device__ __forceinline__ void ldsm4(uint32_t* r, uint32_t addr) {
    asm volatile("ldmatrix.sync.aligned.m8n8.x4.shared.b16 {%0,%1,%2,%3}, [%4];"
        : "=r"(r[0]), "=r"(r[1]), "=r"(r[2]), "=r"(r[3]) : "r"(addr));
}
__device__ __forceinline__ void ldsm4t(uint32_t* r, uint32_t addr) {
    asm volatile("ldmatrix.sync.aligned.m8n8.x4.trans.shared.b16 {%0,%1,%2,%3}, [%4];"
        : "=r"(r[0]), "=r"(r[1]), "=r"(r[2]), "=r"(r[3]) : "r"(addr));
}
__device__ __forceinline__ void ldsm2t(uint32_t& r0, uint32_t& r1, uint32_t addr) {
    asm volatile("ldmatrix.sync.aligned.m8n8.x2.trans.shared.b16 {%0,%1}, [%2];"
        : "=r"(r0), "=r"(r1) : "r"(addr));
}
__device__ __forceinline__ void mma16816(float* c, const uint32_t* a,
                                         uint32_t b0, uint32_t b1) {
    asm volatile(
        "mma.sync.aligned.m16n8k16.row.col.f32.f16.f16.f32 "
        "{%0,%1,%2,%3},{%4,%5,%6,%7},{%8,%9},{%0,%1,%2,%3};"
        : "+f"(c[0]), "+f"(c[1]), "+f"(c[2]), "+f"(c[3])
        : "r"(a[0]), "r"(a[1]), "r"(a[2]), "r"(a[3]), "r"(b0), "r"(b1));
}
__device__ __forceinline__ uint32_t pack_h2(float lo, float hi) {
    uint32_t r;
    asm("cvt.rn.f16x2.f32 %0, %1, %2;" : "=r"(r) : "f"(hi), "f"(lo));
    return r;
}
#define CP_ASYNC16(dst, src) \
    asm volatile("cp.async.cg.shared.global [%0], [%1], 16;" \
                 :: "r"(dst), "l"(src) : "memory")
#define CP_COMMIT() asm volatile("cp.async.commit_group;" ::: "memory")
#define CP_WAIT0()  asm volatile("cp.async.wait_group 0;" ::: "memory")

// ---------------------------------------------------------------------------
// QKV: Y = (X+pos) @ W + b, fp16 out. (unchanged - known good)
// ---------------------------------------------------------------------------
#define ASTR 528                        // bytes per smem row (256h + 8h pad)
#define QKV_AS 0
#define QKV_WS (128 * ASTR)
#define QKV_SMEM (QKV_WS + 256 * ASTR)  // 202752

__global__ __launch_bounds__(256, 1) void qkv_mma(
    const float* __restrict__ x,  const float* __restrict__ pos,
    const float* __restrict__ wq, const float* __restrict__ bq,
    const float* __restrict__ wk, const float* __restrict__ bk,
    const float* __restrict__ wv, const float* __restrict__ bv)
{
    extern __shared__ char smem[];
    const uint32_t sb = smem_u32(smem);
    const int t = threadIdx.x, w = t >> 5, lane = t & 31;
    const int g = lane >> 2, tg = lane & 3;
    const int i8 = lane & 7, s1 = (lane >> 3) & 1, s2 = (lane >> 4) & 1;
    const int jj = lane & 15, ji = jj & 7, js = jj >> 3;

    const int wsel = blockIdx.y;
    const float* W    = (wsel == 0) ? wq : (wsel == 1) ? wk : wv;
    const float* bias = (wsel == 0) ? bq : (wsel == 1) ? bk : bv;
    __half*      outp = (wsel == 0) ? g_Q : (wsel == 1) ? g_K : g_V;

    const int m0 = blockIdx.x * 128;
    const int sbase = m0 % SEQ;

    #pragma unroll
    for (int p = 0; p < 32; p++) {
        int fid = p * 256 + t;
        int row = fid >> 6, c4 = fid & 63;
        float4 xa = *(const float4*)(x   + (size_t)(m0 + row) * DM + c4 * 4);
        float4 pa = *(const float4*)(pos + (size_t)(sbase + row) * DM + c4 * 4);
        uint2 u;
        u.x = pack_h2(xa.x + pa.x, xa.y + pa.y);
        u.y = pack_h2(xa.z + pa.z, xa.w + pa.w);
        *(uint2*)(smem + QKV_AS + row * ASTR + c4 * 8) = u;
    }
    #pragma unroll
    for (int p = 0; p < 64; p++) {
        int fid = p * 256 + t;
        int k = fid >> 6, c4 = fid & 63;
        float4 wv4 = *(const float4*)(W + (size_t)k * DM + c4 * 4);
        uint2 u;
        u.x = pack_h2(wv4.x, wv4.y);
        u.y = pack_h2(wv4.z, wv4.w);
        *(uint2*)(smem + QKV_WS + k * ASTR + c4 * 8) = u;
    }
    __syncthreads();

    const int wm2 = w & 1, wn2 = w >> 1;
    float acc[4][8][4] = {};

    const uint32_t abase = sb + QKV_AS + (64 * wm2 + i8 + s1 * 8) * ASTR + s2 * 16;
    const uint32_t bbase = sb + QKV_WS + (ji + js * 8) * ASTR + (64 * wn2) * 2;

    #pragma unroll
    for (int kk = 0; kk < 16; kk++) {
        uint32_t a[4][4];
        #pragma unroll
        for (int mi = 0; mi < 4; mi++)
            ldsm4(a[mi], abase + mi * 16 * ASTR + kk * 32);
        #pragma unroll
        for (int nt = 0; nt < 8; nt++) {
            uint32_t b0, b1;
            ldsm2t(b0, b1, bbase + kk * 16 * ASTR + nt * 16);
            #pragma unroll
            for (int mi = 0; mi < 4; mi++)
                mma16816(acc[mi][nt], a[mi], b0, b1);
        }
    }

    #pragma unroll
    for (int mi = 0; mi < 4; mi++) {
        int r0 = 64 * wm2 + 16 * mi + g;
        #pragma unroll
        for (int nt = 0; nt < 8; nt++) {
            int col = 64 * wn2 + 8 * nt + 2 * tg;
            float b0v = __ldg(bias + col), b1v = __ldg(bias + col + 1);
            *(uint32_t*)(outp + (size_t)(m0 + r0) * DM + col) =
                pack_h2(acc[mi][nt][0] + b0v, acc[mi][nt][1] + b1v);
            *(uint32_t*)(outp + (size_t)(m0 + r0 + 8) * DM + col) =
                pack_h2(acc[mi][nt][2] + b0v, acc[mi][nt][3] + b1v);
        }
    }
}

// ---------------------------------------------------------------------------
// Attention v4: CTA = 128 q-rows, 512 threads (16 warps), TOK = 64.
// S-phase: 16 warps = 8 row-groups(16r) x 2 token-halves(32t).
// P (128x64 fp16) roundtrips through smem (18 KB).
// O-phase: 16 warps = 2 row-groups(64r) x 8 d-slices(32d):
//          V-fragment duplication drops to 2x; oc = 64 regs/thread.
// K and V double-buffered via cp.async. 2 barriers per chunk.
// ---------------------------------------------------------------------------
#define TOK 64
#define NCHUNK (SEQ / TOK)       // 36
#define PSTR 144                 // P row stride bytes (64h=128B + 16 pad)

#define AQ  0                        // Q  [128][528]   67584
#define AK0 (128 * ASTR)             // K buf0 [64][528]
#define AK1 (AK0 + 64 * ASTR)
#define AV0 (AK1 + 64 * ASTR)
#define AV1 (AV0 + 64 * ASTR)
#define AP  (AV1 + 64 * ASTR)        // P [128][144]    202752
#define ARS (AP + 128 * PSTR)        // rowsum [128][2] f32  221184
#define ATT_SMEM (ARS + 1024)        // 222208

__global__ __launch_bounds__(512, 1) void attn_mma(float* __restrict__ out)
{
    extern __shared__ char smem[];
    const uint32_t sb = smem_u32(smem);
    const int t = threadIdx.x, w = t >> 5, lane = t & 31;
    const int g = lane >> 2, tg = lane & 3;
    const int i8 = lane & 7, s1 = (lane >> 3) & 1, s2 = (lane >> 4) & 1;
    const int q4 = lane >> 3;

    const int qt = blockIdx.x, b = blockIdx.y;
    const __half* Qg = g_Q + ((size_t)b * SEQ + qt * 128) * DM;
    const __half* Kg = g_K + (size_t)b * SEQ * DM;
    const __half* Vg = g_V + (size_t)b * SEQ * DM;

    // prologue: Q tile + K0/V0
    #pragma unroll
    for (int p = 0; p < 8; p++) {
        int q = p * 512 + t;
        int row = q >> 5, gr = q & 31;
        CP_ASYNC16(sb + AQ + row * ASTR + gr * 16,
                   (const char*)Qg + row * 512 + gr * 16);
    }
    #pragma unroll
    for (int p = 0; p < 4; p++) {
        int q = p * 512 + t;
        int row = q >> 5, gr = q & 31;
        CP_ASYNC16(sb + AK0 + row * ASTR + gr * 16,
                   (const char*)Kg + row * 512 + gr * 16);
        CP_ASYNC16(sb + AV0 + row * ASTR + gr * 16,
                   (const char*)Vg + row * 512 + gr * 16);
    }
    CP_COMMIT();

    // S-phase: row-group wr (16 rows), token-half wc (32 tokens)
    const int wr = w & 7, wc = w >> 3;
    // O-phase: row-group wo (64 rows), d-slice wd (32 cols)
    const int wo = w >> 3, wd = w & 7;

    const uint32_t qa_base = sb + AQ + (16 * wr + i8 + s1 * 8) * ASTR + s2 * 16;
    const uint32_t kb_lane = (uint32_t)(((q4 >> 1) * 8 + i8) * ASTR + (q4 & 1) * 16);
    const uint32_t pa_base = sb + AP + (64 * wo + i8 + s1 * 8) * PSTR + s2 * 16;
    const uint32_t vb_lane = (uint32_t)(((q4 & 1) * 8 + i8) * ASTR + (q4 >> 1) * 16
                                        + 64 * wd);

    const int r0s = 16 * wr + g, r1s = r0s + 8;   // S-phase rows

    float oc[4][4][4] = {};      // [m-tile][n8-tile][frag]: 64 regs
    float rs0 = 0.0f, rs1 = 0.0f;
    const float scale = 0.0625f; // 1/sqrt(256)

    for (int kt = 0; kt < NCHUNK; kt++) {
        CP_WAIT0();
        __syncthreads();
        const uint32_t kbuf = sb + (kt & 1 ? AK1 : AK0);
        const uint32_t vbuf = sb + (kt & 1 ? AV1 : AV0);

        // prefetch next K/V
        if (kt + 1 < NCHUNK) {
            const __half* Kt = Kg + (size_t)(kt + 1) * TOK * DM;
            const __half* Vt = Vg + (size_t)(kt + 1) * TOK * DM;
            const uint32_t kdst = sb + ((kt + 1) & 1 ? AK1 : AK0);
            const uint32_t vdst = sb + ((kt + 1) & 1 ? AV1 : AV0);
            #pragma unroll
            for (int p = 0; p < 4; p++) {
                int q = p * 512 + t;
                int row = q >> 5, gr = q & 31;
                CP_ASYNC16(kdst + row * ASTR + gr * 16,
                           (const char*)Kt + row * 512 + gr * 16);
                CP_ASYNC16(vdst + row * ASTR + gr * 16,
                           (const char*)Vt + row * 512 + gr * 16);
            }
        }
        CP_COMMIT();

        // ---- S = Q K^T : 16 rows x 32 tokens (this warp's half), K-dim 256 ----
        float sc[4][4] = {};
        #pragma unroll
        for (int kk = 0; kk < 16; kk++) {
            uint32_t a[4];
            ldsm4(a, qa_base + kk * 32);
            uint32_t bb[4];
            ldsm4(bb, kbuf + (uint32_t)(32 * wc) * ASTR + kb_lane + kk * 32);
            mma16816(sc[0], a, bb[0], bb[1]);
            mma16816(sc[1], a, bb[2], bb[3]);
            ldsm4(bb, kbuf + (uint32_t)(32 * wc + 16) * ASTR + kb_lane + kk * 32);
            mma16816(sc[2], a, bb[0], bb[1]);
            mma16816(sc[3], a, bb[2], bb[3]);
        }

        // ---- exp -> P smem (fp16), accumulate rowsum ----
        #pragma unroll
        for (int nt = 0; nt < 4; nt++) {
            int tok = 32 * wc + 8 * nt + 2 * tg;
            float e00 = __expf(sc[nt][0] * scale);
            float e01 = __expf(sc[nt][1] * scale);
            float e10 = __expf(sc[nt][2] * scale);
            float e11 = __expf(sc[nt][3] * scale);
            rs0 += e00 + e01;
            rs1 += e10 + e11;
            *(uint32_t*)(smem + AP + r0s * PSTR + tok * 2) = pack_h2(e00, e01);
            *(uint32_t*)(smem + AP + r1s * PSTR + tok * 2) = pack_h2(e10, e11);
        }
        __syncthreads();

        // ---- O += P V : 64 rows x 32 d (this warp's slice), k-dim 64 ----
        #pragma unroll
        for (int kk2 = 0; kk2 < 4; kk2++) {
            uint32_t pa[4][4];
            #pragma unroll
            for (int mi = 0; mi < 4; mi++)
                ldsm4(pa[mi], pa_base + mi * 16 * PSTR + kk2 * 32);
            #pragma unroll
            for (int np = 0; np < 2; np++) {
                uint32_t bb[4];
                ldsm4t(bb, vbuf + (uint32_t)(kk2 * 16) * ASTR + vb_lane + np * 32);
                #pragma unroll
                for (int mi = 0; mi < 4; mi++) {
                    mma16816(oc[mi][2 * np],     pa[mi], bb[0], bb[1]);
                    mma16816(oc[mi][2 * np + 1], pa[mi], bb[2], bb[3]);
                }
            }
        }
    }

    // ---- rowsum: reduce over tg lanes, combine the two token-half warps ----
    rs0 += __shfl_xor_sync(0xffffffffu, rs0, 1);
    rs0 += __shfl_xor_sync(0xffffffffu, rs0, 2);
    rs1 += __shfl_xor_sync(0xffffffffu, rs1, 1);
    rs1 += __shfl_xor_sync(0xffffffffu, rs1, 2);
    float* rsum = (float*)(smem + ARS);
    if (tg == 0) {
        rsum[r0s * 2 + wc] = rs0;
        rsum[r1s * 2 + wc] = rs1;
    }
    __syncthreads();

    // ---- output: rows 64*wo..+63, cols 32*wd..+31 ----
    float* ob = out + ((size_t)b * SEQ + qt * 128) * DM;
    #pragma unroll
    for (int mi = 0; mi < 4; mi++) {
        int r0 = 64 * wo + 16 * mi + g;
        int r1 = r0 + 8;
        float inv0 = 1.0f / (rsum[r0 * 2] + rsum[r0 * 2 + 1]);
        float inv1 = 1.0f / (rsum[r1 * 2] + rsum[r1 * 2 + 1]);
        #pragma unroll
        for (int nt = 0; nt < 4; nt++) {
            int col = 32 * wd + 8 * nt + 2 * tg;
            *(float2*)(ob + (size_t)r0 * DM + col) =
                make_float2(oc[mi][nt][0] * inv0, oc[mi][nt][1] * inv0);
            *(float2*)(ob + (size_t)r1 * DM + col) =
                make_float2(oc[mi][nt][2] * inv1, oc[mi][nt][3] * inv1);
        }
    }
}

extern "C" void kernel_launch(void* const* d_in, const int* in_sizes, int n_in,
                              void* d_out, int out_size)
{
    const float* x   = (const float*)d_in[0];
    const float* wq  = (const float*)d_in[1];
    const float* bq  = (const float*)d_in[2];
    const float* wk  = (const float*)d_in[3];
    const float* bk  = (const float*)d_in[4];
    const float* wv  = (const float*)d_in[5];
    const float* bv  = (const float*)d_in[6];
    const float* pos = (const float*)d_in[7];
    float* out = (float*)d_out;

    cudaFuncSetAttribute(qkv_mma, cudaFuncAttributeMaxDynamicSharedMemorySize,
                         QKV_SMEM);
    cudaFuncSetAttribute(attn_mma, cudaFuncAttributeMaxDynamicSharedMemorySize,
                         ATT_SMEM);

    qkv_mma<<<dim3((NB * SEQ) / 128, 3), 256, QKV_SMEM>>>(
        x, pos, wq, bq, wk, bk, wv, bv);
    attn_mma<<<dim3(SEQ / 128, NB), 512, ATT_SMEM>>>(out);
}